// round 1
// baseline (speedup 1.0000x reference)
#include <cuda_runtime.h>
#include <math.h>

#define N2   542            // padded image size (512 + 30)
#define NH   272            // N2/2 + 1 (Hermitian half along columns)
#define NPIX (N2*N2)
#define HPIX (N2*NH)
#define NB   24             // B*C images
#define BATCH 8
#define CH   3
#define HIN  512
#define KH   31
#define PH   15
#define FS   3
#define NF   8
#define L1   541            // N2-1, used by edgetaper alpha

// ---------------- device global scratch (no dynamic allocation allowed) ----
__device__ float g_Wfr[NPIX], g_Wfi[NPIX];          // forward DFT matrix e^{-2pi i jk/N}
__device__ float g_Wir[NPIX], g_Wii[NPIX];          // inverse DFT matrix e^{+2pi i jk/N}/N
__device__ float g_W2r[NH*N2], g_W2i[NH*N2];        // weighted inverse for Hermitian axis [v][n]
__device__ float g_x  [NB*NPIX];                    // current real image (padded)
__device__ float g_Gr [NB*HPIX], g_Gi [NB*HPIX];    // forward stage-1 (cols transformed, half)
__device__ float g_Fr [NB*HPIX], g_Fi [NB*HPIX];    // spectrum (all u, half v)
__device__ float g_Zr [NB*HPIX], g_Zi [NB*HPIX];    // inverse stage-1
__device__ float g_Dkr[BATCH*HPIX], g_Dki[BATCH*HPIX];  // blur OTF per batch (half grid)
__device__ float g_Dg [CH*HPIX];                    // sum_f |Dg|^2 per channel (half grid)
__device__ float g_v0 [BATCH*N2], g_v1 [BATCH*N2];  // edgetaper separable window vectors
__device__ float g_Er [N2*KH], g_Ei [N2*KH];        // e^{-2pi i u (t-15)/N} table
__device__ float g_E3r[N2*FS], g_E3i[N2*FS];        // e^{-2pi i u (t-1)/N} table
__device__ float g_Tr [BATCH*N2*KH], g_Ti[BATCH*N2*KH]; // Dk stage-a temp [b][u][j]

// ---------------- setup kernels -------------------------------------------
__global__ void k_buildW() {
    int idx = blockIdx.x * blockDim.x + threadIdx.x;
    if (idx >= NPIX) return;
    int kc = idx % N2, j = idx / N2;
    long t = ((long)j * kc) % N2;
    double sn, cs;
    sincospi(2.0 * (double)t / (double)N2, &sn, &cs);
    g_Wfr[idx] = (float)cs;            g_Wfi[idx] = (float)(-sn);
    g_Wir[idx] = (float)(cs / N2);     g_Wii[idx] = (float)(sn / N2);
}

__global__ void k_buildW2() {
    int idx = blockIdx.x * blockDim.x + threadIdx.x;
    if (idx >= NH * N2) return;
    int n = idx % N2, v = idx / N2;
    long t = ((long)v * n) % N2;
    double sn, cs;
    sincospi(2.0 * (double)t / (double)N2, &sn, &cs);
    double w = ((v == 0) || (v == NH - 1)) ? (1.0 / N2) : (2.0 / N2);
    g_W2r[idx] = (float)(cs * w);
    g_W2i[idx] = (float)(sn * w);
}

__global__ void k_buildE() {
    int idx = blockIdx.x * blockDim.x + threadIdx.x;
    if (idx >= N2 * KH) return;
    int t = idx % KH, u = idx / KH;
    long m = ((long)u * (t - PH)) % N2; if (m < 0) m += N2;
    double sn, cs;
    sincospi(2.0 * (double)m / (double)N2, &sn, &cs);
    g_Er[idx] = (float)cs; g_Ei[idx] = (float)(-sn);
}

__global__ void k_buildE3() {
    int idx = blockIdx.x * blockDim.x + threadIdx.x;
    if (idx >= N2 * FS) return;
    int t = idx % FS, u = idx / FS;
    long m = ((long)u * (t - 1)) % N2; if (m < 0) m += N2;
    double sn, cs;
    sincospi(2.0 * (double)m / (double)N2, &sn, &cs);
    g_E3r[idx] = (float)cs; g_E3i[idx] = (float)(-sn);
}

__global__ void k_pad(const float* __restrict__ y) {
    int idx = blockIdx.x * blockDim.x + threadIdx.x;
    if (idx >= NB * NPIX) return;
    int jj = idx % N2, ii = (idx / N2) % N2, img = idx / NPIX;
    int si = min(max(ii - PH, 0), HIN - 1);
    int sj = min(max(jj - PH, 0), HIN - 1);
    g_x[idx] = y[(long)img * HIN * HIN + si * HIN + sj];
}

// edgetaper window: per (batch, axis): proj -> |FFT_541|^2 -> IFFT_541 -> 1 - c/max
__global__ void k_alpha(const float* __restrict__ kk) {
    int b = blockIdx.x >> 1;
    int axis = blockIdx.x & 1;
    __shared__ float proj[KH];
    __shared__ float p[L1];
    __shared__ float cb[L1];
    __shared__ float red[576];
    int tid = threadIdx.x;

    if (tid < KH) {
        float s = 0.f;
        const float* kb = kk + b * KH * KH;
        for (int t = 0; t < KH; t++)
            s += (axis == 0) ? kb[tid * KH + t] : kb[t * KH + tid];
        proj[tid] = s;
    }
    __syncthreads();

    if (tid < L1) {
        double zr = 0.0, zi = 0.0;
        for (int t = 0; t < KH; t++) {
            int m = (tid * t) % L1;
            double sn, cs;
            sincospi(2.0 * (double)m / (double)L1, &sn, &cs);
            zr += proj[t] * cs;
            zi -= proj[t] * sn;
        }
        p[tid] = (float)(zr * zr + zi * zi);
    }
    __syncthreads();

    if (tid < L1) {
        double acc = 0.0;
        for (int m = 0; m < L1; m++) {
            int mm = (m * tid) % L1;
            double sn, cs;
            sincospi(2.0 * (double)mm / (double)L1, &sn, &cs);
            acc += (double)p[m] * cs;
        }
        cb[tid] = (float)(acc / (double)L1);
    }
    red[tid] = (tid < L1) ? cb[tid] : -1e30f;
    __syncthreads();
    for (int s = 512; s > 0; s >>= 1) {
        if (tid < s && tid + s < 576) red[tid] = fmaxf(red[tid], red[tid + s]);
        __syncthreads();
    }
    float mx = red[0];
    float* v = (axis == 0) ? (g_v0 + b * N2) : (g_v1 + b * N2);
    if (tid < L1) v[tid] = 1.f - cb[tid] / mx;
    if (tid == 0) v[L1] = 1.f - cb[0] / mx;
}

// Dk OTF, separable two-stage direct DFT from 31x31 taps
__global__ void k_dk_a(const float* __restrict__ kk) {
    int idx = blockIdx.x * blockDim.x + threadIdx.x;
    if (idx >= BATCH * N2 * KH) return;
    int j = idx % KH;
    int u = (idx / KH) % N2;
    int b = idx / (KH * N2);
    float tr = 0.f, ti = 0.f;
    for (int i = 0; i < KH; i++) {
        float w = kk[b * KH * KH + i * KH + j];
        tr += w * g_Er[u * KH + i];
        ti += w * g_Ei[u * KH + i];
    }
    g_Tr[idx] = tr; g_Ti[idx] = ti;
}

__global__ void k_dk_b() {
    int idx = blockIdx.x * blockDim.x + threadIdx.x;
    if (idx >= BATCH * HPIX) return;
    int v = idx % NH;
    int u = (idx / NH) % N2;
    int b = idx / HPIX;
    float dr = 0.f, di = 0.f;
    const float* tr = g_Tr + (b * N2 + u) * KH;
    const float* ti = g_Ti + (b * N2 + u) * KH;
    for (int j = 0; j < KH; j++) {
        float er = g_Er[v * KH + j], ei = g_Ei[v * KH + j];
        dr += tr[j] * er - ti[j] * ei;
        di += tr[j] * ei + ti[j] * er;
    }
    g_Dkr[idx] = dr; g_Dki[idx] = di;
}

// sum over filters of |Dg|^2 per channel
__global__ void k_dg(const float* __restrict__ filt) {
    int idx = blockIdx.x * blockDim.x + threadIdx.x;
    if (idx >= CH * HPIX) return;
    int v = idx % NH;
    int u = (idx / NH) % N2;
    int c = idx / HPIX;
    float eur[FS], eui[FS], evr[FS], evi[FS];
    for (int t = 0; t < FS; t++) {
        eur[t] = g_E3r[u * FS + t]; eui[t] = g_E3i[u * FS + t];
        evr[t] = g_E3r[v * FS + t]; evi[t] = g_E3i[v * FS + t];
    }
    float acc = 0.f;
    for (int f = 0; f < NF; f++) {
        float cr = 0.f, ci = 0.f;
        for (int i = 0; i < FS; i++)
            for (int j = 0; j < FS; j++) {
                float w = filt[((f * CH + c) * FS + i) * FS + j];
                float er = eur[i] * evr[j] - eui[i] * evi[j];
                float ei = eur[i] * evi[j] + eui[i] * evr[j];
                cr += w * er; ci += w * ei;
            }
        acc += cr * cr + ci * ci;
    }
    g_Dg[idx] = acc;
}

// pointwise spectrum ops
__global__ void k_p1() {
    int idx = blockIdx.x * blockDim.x + threadIdx.x;
    if (idx >= NB * HPIX) return;
    int uv = idx % HPIX;
    int b = (idx / HPIX) / CH;
    float dr = g_Dkr[b * HPIX + uv], di = g_Dki[b * HPIX + uv];
    float fr = g_Fr[idx], fi = g_Fi[idx];
    g_Fr[idx] = fr * dr - fi * di;
    g_Fi[idx] = fr * di + fi * dr;
}

__global__ void k_p3(const float* __restrict__ lam) {
    int idx = blockIdx.x * blockDim.x + threadIdx.x;
    if (idx >= NB * HPIX) return;
    float el = expf(lam[0]);
    int uv = idx % HPIX;
    int img = idx / HPIX;
    int b = img / CH, c = img % CH;
    float dr = g_Dkr[b * HPIX + uv], di = g_Dki[b * HPIX + uv];
    float om = 1.f / (dr * dr + di * di + el * g_Dg[c * HPIX + uv]);
    float mr = dr * om, mi = -di * om;
    float fr = g_Fr[idx], fi = g_Fi[idx];
    g_Fr[idx] = fr * mr - fi * mi;
    g_Fi[idx] = fr * mi + fi * mr;
}

// ---------------- generic batched (complex) GEMM --------------------------
// MODE 0: C(cplx) = A(real, batched) * B(cplx, shared)
// MODE 1: C(cplx) = A(cplx, shared) * B(cplx, batched)
// MODE 2: C(real) = Re( A(cplx, batched) * B(cplx, shared) ), optional blend
template<int MODE, bool BLEND>
__global__ void __launch_bounds__(256) k_gemm(
    const float* __restrict__ Apr, const float* __restrict__ Api, long sA,
    const float* __restrict__ Bpr, const float* __restrict__ Bpi, long sB,
    float* Cpr, float* Cpi, long sC,
    int M, int Nn, int K, int lda, int ldb, int ldc,
    const float* __restrict__ v0, const float* __restrict__ v1)
{
    __shared__ float sAr[16][68];
    __shared__ float sAi[16][68];
    __shared__ float sBr[16][68];
    __shared__ float sBi[16][68];

    const int z = blockIdx.z;
    const float* Ar = Apr + (long)z * sA;
    const float* Ai = (MODE != 0) ? (Api + (long)z * sA) : nullptr;
    const float* Br = Bpr + (long)z * sB;
    const float* Bi = Bpi + (long)z * sB;
    float* Cr = Cpr + (long)z * sC;
    float* Ci = (MODE == 2) ? nullptr : (Cpi + (long)z * sC);

    const int row0 = blockIdx.y * 64;
    const int col0 = blockIdx.x * 64;
    const int tx = threadIdx.x, ty = threadIdx.y;
    const int tid = ty * 16 + tx;

    float accr[4][4] = {};
    float acci[4][4] = {};

    const int am = tid >> 2;         // 0..63 (A tile row)
    const int ak = (tid & 3) * 4;    // 0,4,8,12 (A tile k)
    const int bk = tid >> 4;         // 0..15 (B tile k)
    const int bn = (tid & 15) * 4;   // 0..60 (B tile col)

    for (int k0 = 0; k0 < K; k0 += 16) {
        // A tile -> transposed smem [k][m]
        {
            int row = row0 + am;
            bool rok = (row < M);
            #pragma unroll
            for (int s = 0; s < 2; s++) {
                int kkg = k0 + ak + 2 * s;
                float2 vr = make_float2(0.f, 0.f), vi = make_float2(0.f, 0.f);
                if (rok && kkg < K) {
                    vr = *(const float2*)(Ar + (long)row * lda + kkg);
                    if (MODE != 0) vi = *(const float2*)(Ai + (long)row * lda + kkg);
                }
                sAr[ak + 2 * s][am] = vr.x; sAr[ak + 2 * s + 1][am] = vr.y;
                if (MODE != 0) {
                    sAi[ak + 2 * s][am] = vi.x; sAi[ak + 2 * s + 1][am] = vi.y;
                }
            }
        }
        // B tile [k][n]
        {
            int krow = k0 + bk;
            bool kok = (krow < K);
            #pragma unroll
            for (int s = 0; s < 2; s++) {
                int col = col0 + bn + 2 * s;
                float2 vr = make_float2(0.f, 0.f), vi = make_float2(0.f, 0.f);
                if (kok && col < Nn) {
                    vr = *(const float2*)(Br + (long)krow * ldb + col);
                    vi = *(const float2*)(Bi + (long)krow * ldb + col);
                }
                sBr[bk][bn + 2 * s] = vr.x; sBr[bk][bn + 2 * s + 1] = vr.y;
                sBi[bk][bn + 2 * s] = vi.x; sBi[bk][bn + 2 * s + 1] = vi.y;
            }
        }
        __syncthreads();

        #pragma unroll
        for (int kk = 0; kk < 16; kk++) {
            float ar[4], aiv[4], br[4], biv[4];
            *(float4*)ar  = *(const float4*)&sAr[kk][ty * 4];
            if (MODE != 0) *(float4*)aiv = *(const float4*)&sAi[kk][ty * 4];
            *(float4*)br  = *(const float4*)&sBr[kk][tx * 4];
            *(float4*)biv = *(const float4*)&sBi[kk][tx * 4];
            #pragma unroll
            for (int i = 0; i < 4; i++)
                #pragma unroll
                for (int j = 0; j < 4; j++) {
                    if (MODE == 0) {
                        accr[i][j] += ar[i] * br[j];
                        acci[i][j] += ar[i] * biv[j];
                    } else if (MODE == 1) {
                        accr[i][j] += ar[i] * br[j] - aiv[i] * biv[j];
                        acci[i][j] += ar[i] * biv[j] + aiv[i] * br[j];
                    } else {
                        accr[i][j] += ar[i] * br[j] - aiv[i] * biv[j];
                    }
                }
        }
        __syncthreads();
    }

    const float* v0b = nullptr;
    const float* v1b = nullptr;
    if (BLEND) { v0b = v0 + (z / CH) * N2; v1b = v1 + (z / CH) * N2; }

    #pragma unroll
    for (int i = 0; i < 4; i++) {
        int row = row0 + ty * 4 + i;
        if (row >= M) continue;
        #pragma unroll
        for (int j = 0; j < 4; j++) {
            int col = col0 + tx * 4 + j;
            if (col >= Nn) continue;
            long off = (long)row * ldc + col;
            if (MODE == 2) {
                if (BLEND) {
                    float a = v0b[row] * v1b[col];
                    Cr[off] = a * Cr[off] + (1.f - a) * accr[i][j];
                } else {
                    Cr[off] = accr[i][j];
                }
            } else {
                Cr[off] = accr[i][j];
                Ci[off] = acci[i][j];
            }
        }
    }
}

// ---------------- host orchestration --------------------------------------
extern "C" void kernel_launch(void* const* d_in, const int* in_sizes, int n_in,
                              void* d_out, int out_size)
{
    const float *y = nullptr, *kk = nullptr, *lam = nullptr, *filt = nullptr;
    for (int i = 0; i < n_in; i++) {
        if      (in_sizes[i] == BATCH * CH * HIN * HIN) y    = (const float*)d_in[i];
        else if (in_sizes[i] == BATCH * KH * KH)        kk   = (const float*)d_in[i];
        else if (in_sizes[i] == 1)                      lam  = (const float*)d_in[i];
        else if (in_sizes[i] == NF * CH * FS * FS)      filt = (const float*)d_in[i];
    }
    float* out = (float*)d_out;

    float *Wfr, *Wfi, *Wir, *Wii, *W2r, *W2i, *x, *Gr, *Gi, *Fr, *Fi, *Zr, *Zi, *v0, *v1;
    cudaGetSymbolAddress((void**)&Wfr, g_Wfr);
    cudaGetSymbolAddress((void**)&Wfi, g_Wfi);
    cudaGetSymbolAddress((void**)&Wir, g_Wir);
    cudaGetSymbolAddress((void**)&Wii, g_Wii);
    cudaGetSymbolAddress((void**)&W2r, g_W2r);
    cudaGetSymbolAddress((void**)&W2i, g_W2i);
    cudaGetSymbolAddress((void**)&x,   g_x);
    cudaGetSymbolAddress((void**)&Gr,  g_Gr);
    cudaGetSymbolAddress((void**)&Gi,  g_Gi);
    cudaGetSymbolAddress((void**)&Fr,  g_Fr);
    cudaGetSymbolAddress((void**)&Fi,  g_Fi);
    cudaGetSymbolAddress((void**)&Zr,  g_Zr);
    cudaGetSymbolAddress((void**)&Zi,  g_Zi);
    cudaGetSymbolAddress((void**)&v0,  g_v0);
    cudaGetSymbolAddress((void**)&v1,  g_v1);

    const int tpb = 256;
    k_buildW <<<(NPIX + tpb - 1) / tpb, tpb>>>();
    k_buildW2<<<(NH * N2 + tpb - 1) / tpb, tpb>>>();
    k_buildE <<<(N2 * KH + tpb - 1) / tpb, tpb>>>();
    k_buildE3<<<(N2 * FS + tpb - 1) / tpb, tpb>>>();
    k_pad    <<<(NB * NPIX + tpb - 1) / tpb, tpb>>>(y);
    k_alpha  <<<2 * BATCH, 576>>>(kk);
    k_dk_a   <<<(BATCH * N2 * KH + tpb - 1) / tpb, tpb>>>(kk);
    k_dk_b   <<<(BATCH * HPIX + tpb - 1) / tpb, tpb>>>();
    k_dg     <<<(CH * HPIX + tpb - 1) / tpb, tpb>>>(filt);

    dim3 blk(16, 16);
    dim3 gFwd((NH + 63) / 64, (N2 + 63) / 64, NB);   // 5 x 9 x 24
    dim3 gInv2((N2 + 63) / 64, (N2 + 63) / 64, NB);  // 9 x 9 x 24
    int gpw = (NB * HPIX + tpb - 1) / tpb;

    for (int it = 0; it < 4; it++) {
        bool last = (it == 3);
        // forward stage 1: G[m,v] = sum_n x[m,n] * Wf[n,v]  (half columns)
        k_gemm<0, false><<<gFwd, blk>>>(x, nullptr, (long)NPIX,
                                        Wfr, Wfi, 0L,
                                        Gr, Gi, (long)HPIX,
                                        N2, NH, N2, N2, N2, NH, nullptr, nullptr);
        // forward stage 2: F[u,v] = sum_m Wf[u,m] * G[m,v]
        k_gemm<1, false><<<gFwd, blk>>>(Wfr, Wfi, 0L,
                                        Gr, Gi, (long)HPIX,
                                        Fr, Fi, (long)HPIX,
                                        N2, NH, N2, N2, NH, NH, nullptr, nullptr);
        if (!last) k_p1<<<gpw, tpb>>>();
        else       k_p3<<<gpw, tpb>>>(lam);
        // inverse stage 1: Z[m,v] = sum_u Wi[m,u] * F[u,v]
        k_gemm<1, false><<<gFwd, blk>>>(Wir, Wii, 0L,
                                        Fr, Fi, (long)HPIX,
                                        Zr, Zi, (long)HPIX,
                                        N2, NH, N2, N2, NH, NH, nullptr, nullptr);
        // inverse stage 2 (real): x/out[m,n] = Re( sum_v Z[m,v] * W2[v,n] )
        if (!last)
            k_gemm<2, true><<<gInv2, blk>>>(Zr, Zi, (long)HPIX,
                                            W2r, W2i, 0L,
                                            x, nullptr, (long)NPIX,
                                            N2, N2, NH, NH, N2, N2, v0, v1);
        else
            k_gemm<2, false><<<gInv2, blk>>>(Zr, Zi, (long)HPIX,
                                             W2r, W2i, 0L,
                                             out, nullptr, (long)NPIX,
                                             N2, N2, NH, NH, N2, N2, nullptr, nullptr);
    }
    (void)out_size;
}

// round 2
// speedup vs baseline: 1.0002x; 1.0002x over previous
#include <cuda_runtime.h>
#include <math.h>

#define N2   542            // padded image size (512 + 30)
#define NH   272            // N2/2 + 1 (Hermitian half along columns)
#define NPIX (N2*N2)
#define HPIX (N2*NH)
#define NB   24             // B*C images
#define BATCH 8
#define CH   3
#define HIN  512
#define KH   31
#define PH   15
#define FS   3
#define NF   8
#define L1   541            // N2-1, used by edgetaper alpha

// ---------------- device global scratch (no dynamic allocation allowed) ----
__device__ float g_Wfr[NPIX], g_Wfi[NPIX];          // forward DFT matrix e^{-2pi i jk/N}
__device__ float g_Wir[NPIX], g_Wii[NPIX];          // inverse DFT matrix e^{+2pi i jk/N}/N
__device__ float g_W2r[NH*N2], g_W2i[NH*N2];        // weighted inverse for Hermitian axis [v][n]
__device__ float g_x  [NB*NPIX];                    // current real image (padded)
__device__ float g_Gr [NB*HPIX], g_Gi [NB*HPIX];    // forward stage-1 (cols transformed, half)
__device__ float g_Fr [NB*HPIX], g_Fi [NB*HPIX];    // spectrum (all u, half v)
__device__ float g_Zr [NB*HPIX], g_Zi [NB*HPIX];    // inverse stage-1
__device__ float g_Dkr[BATCH*HPIX], g_Dki[BATCH*HPIX];  // blur OTF per batch (half grid)
__device__ float g_Dg [CH*HPIX];                    // sum_f |Dg|^2 per channel (half grid)
__device__ float g_v0 [BATCH*N2], g_v1 [BATCH*N2];  // edgetaper separable window vectors
__device__ float g_Er [N2*KH], g_Ei [N2*KH];        // e^{-2pi i u (t-15)/N} table
__device__ float g_E3r[N2*FS], g_E3i[N2*FS];        // e^{-2pi i u (t-1)/N} table
__device__ float g_Tr [BATCH*N2*KH], g_Ti[BATCH*N2*KH]; // Dk stage-a temp [b][u][j]

// ---------------- setup kernels -------------------------------------------
__global__ void k_buildW() {
    int idx = blockIdx.x * blockDim.x + threadIdx.x;
    if (idx >= NPIX) return;
    int kc = idx % N2, j = idx / N2;
    long t = ((long)j * kc) % N2;
    double sn, cs;
    sincospi(2.0 * (double)t / (double)N2, &sn, &cs);
    g_Wfr[idx] = (float)cs;            g_Wfi[idx] = (float)(-sn);
    g_Wir[idx] = (float)(cs / N2);     g_Wii[idx] = (float)(sn / N2);
}

__global__ void k_buildW2() {
    int idx = blockIdx.x * blockDim.x + threadIdx.x;
    if (idx >= NH * N2) return;
    int n = idx % N2, v = idx / N2;
    long t = ((long)v * n) % N2;
    double sn, cs;
    sincospi(2.0 * (double)t / (double)N2, &sn, &cs);
    double w = ((v == 0) || (v == NH - 1)) ? (1.0 / N2) : (2.0 / N2);
    g_W2r[idx] = (float)(cs * w);
    g_W2i[idx] = (float)(sn * w);
}

__global__ void k_buildE() {
    int idx = blockIdx.x * blockDim.x + threadIdx.x;
    if (idx >= N2 * KH) return;
    int t = idx % KH, u = idx / KH;
    long m = ((long)u * (t - PH)) % N2; if (m < 0) m += N2;
    double sn, cs;
    sincospi(2.0 * (double)m / (double)N2, &sn, &cs);
    g_Er[idx] = (float)cs; g_Ei[idx] = (float)(-sn);
}

__global__ void k_buildE3() {
    int idx = blockIdx.x * blockDim.x + threadIdx.x;
    if (idx >= N2 * FS) return;
    int t = idx % FS, u = idx / FS;
    long m = ((long)u * (t - 1)) % N2; if (m < 0) m += N2;
    double sn, cs;
    sincospi(2.0 * (double)m / (double)N2, &sn, &cs);
    g_E3r[idx] = (float)cs; g_E3i[idx] = (float)(-sn);
}

__global__ void k_pad(const float* __restrict__ y) {
    int idx = blockIdx.x * blockDim.x + threadIdx.x;
    if (idx >= NB * NPIX) return;
    int jj = idx % N2, ii = (idx / N2) % N2, img = idx / NPIX;
    int si = min(max(ii - PH, 0), HIN - 1);
    int sj = min(max(jj - PH, 0), HIN - 1);
    g_x[idx] = y[(long)img * HIN * HIN + si * HIN + sj];
}

// edgetaper window: per (batch, axis): proj -> |FFT_541|^2 -> IFFT_541 -> 1 - c/max
__global__ void k_alpha(const float* __restrict__ kk) {
    int b = blockIdx.x >> 1;
    int axis = blockIdx.x & 1;
    __shared__ float proj[KH];
    __shared__ float p[L1];
    __shared__ float cb[L1];
    __shared__ float red[576];
    int tid = threadIdx.x;

    if (tid < KH) {
        float s = 0.f;
        const float* kb = kk + b * KH * KH;
        for (int t = 0; t < KH; t++)
            s += (axis == 0) ? kb[tid * KH + t] : kb[t * KH + tid];
        proj[tid] = s;
    }
    __syncthreads();

    if (tid < L1) {
        double zr = 0.0, zi = 0.0;
        for (int t = 0; t < KH; t++) {
            int m = (tid * t) % L1;
            double sn, cs;
            sincospi(2.0 * (double)m / (double)L1, &sn, &cs);
            zr += proj[t] * cs;
            zi -= proj[t] * sn;
        }
        p[tid] = (float)(zr * zr + zi * zi);
    }
    __syncthreads();

    if (tid < L1) {
        double acc = 0.0;
        for (int m = 0; m < L1; m++) {
            int mm = (m * tid) % L1;
            double sn, cs;
            sincospi(2.0 * (double)mm / (double)L1, &sn, &cs);
            acc += (double)p[m] * cs;
        }
        cb[tid] = (float)(acc / (double)L1);
    }
    red[tid] = (tid < L1) ? cb[tid] : -1e30f;
    __syncthreads();
    for (int s = 512; s > 0; s >>= 1) {
        if (tid < s && tid + s < 576) red[tid] = fmaxf(red[tid], red[tid + s]);
        __syncthreads();
    }
    float mx = red[0];
    float* v = (axis == 0) ? (g_v0 + b * N2) : (g_v1 + b * N2);
    if (tid < L1) v[tid] = 1.f - cb[tid] / mx;
    if (tid == 0) v[L1] = 1.f - cb[0] / mx;
}

// Dk OTF, separable two-stage direct DFT from 31x31 taps
__global__ void k_dk_a(const float* __restrict__ kk) {
    int idx = blockIdx.x * blockDim.x + threadIdx.x;
    if (idx >= BATCH * N2 * KH) return;
    int j = idx % KH;
    int u = (idx / KH) % N2;
    int b = idx / (KH * N2);
    float tr = 0.f, ti = 0.f;
    for (int i = 0; i < KH; i++) {
        float w = kk[b * KH * KH + i * KH + j];
        tr += w * g_Er[u * KH + i];
        ti += w * g_Ei[u * KH + i];
    }
    g_Tr[idx] = tr; g_Ti[idx] = ti;
}

__global__ void k_dk_b() {
    int idx = blockIdx.x * blockDim.x + threadIdx.x;
    if (idx >= BATCH * HPIX) return;
    int v = idx % NH;
    int u = (idx / NH) % N2;
    int b = idx / HPIX;
    float dr = 0.f, di = 0.f;
    const float* tr = g_Tr + (b * N2 + u) * KH;
    const float* ti = g_Ti + (b * N2 + u) * KH;
    for (int j = 0; j < KH; j++) {
        float er = g_Er[v * KH + j], ei = g_Ei[v * KH + j];
        dr += tr[j] * er - ti[j] * ei;
        di += tr[j] * ei + ti[j] * er;
    }
    g_Dkr[idx] = dr; g_Dki[idx] = di;
}

// sum over filters of |Dg|^2 per channel
__global__ void k_dg(const float* __restrict__ filt) {
    int idx = blockIdx.x * blockDim.x + threadIdx.x;
    if (idx >= CH * HPIX) return;
    int v = idx % NH;
    int u = (idx / NH) % N2;
    int c = idx / HPIX;
    float eur[FS], eui[FS], evr[FS], evi[FS];
    for (int t = 0; t < FS; t++) {
        eur[t] = g_E3r[u * FS + t]; eui[t] = g_E3i[u * FS + t];
        evr[t] = g_E3r[v * FS + t]; evi[t] = g_E3i[v * FS + t];
    }
    float acc = 0.f;
    for (int f = 0; f < NF; f++) {
        float cr = 0.f, ci = 0.f;
        for (int i = 0; i < FS; i++)
            for (int j = 0; j < FS; j++) {
                float w = filt[((f * CH + c) * FS + i) * FS + j];
                float er = eur[i] * evr[j] - eui[i] * evi[j];
                float ei = eur[i] * evi[j] + eui[i] * evr[j];
                cr += w * er; ci += w * ei;
            }
        acc += cr * cr + ci * ci;
    }
    g_Dg[idx] = acc;
}

// pointwise spectrum ops
__global__ void k_p1() {
    int idx = blockIdx.x * blockDim.x + threadIdx.x;
    if (idx >= NB * HPIX) return;
    int uv = idx % HPIX;
    int b = (idx / HPIX) / CH;
    float dr = g_Dkr[b * HPIX + uv], di = g_Dki[b * HPIX + uv];
    float fr = g_Fr[idx], fi = g_Fi[idx];
    g_Fr[idx] = fr * dr - fi * di;
    g_Fi[idx] = fr * di + fi * dr;
}

__global__ void k_p3(const float* __restrict__ lam) {
    int idx = blockIdx.x * blockDim.x + threadIdx.x;
    if (idx >= NB * HPIX) return;
    float el = expf(lam[0]);
    int uv = idx % HPIX;
    int img = idx / HPIX;
    int b = img / CH, c = img % CH;
    float dr = g_Dkr[b * HPIX + uv], di = g_Dki[b * HPIX + uv];
    float om = 1.f / (dr * dr + di * di + el * g_Dg[c * HPIX + uv]);
    float mr = dr * om, mi = -di * om;
    float fr = g_Fr[idx], fi = g_Fi[idx];
    g_Fr[idx] = fr * mr - fi * mi;
    g_Fi[idx] = fr * mi + fi * mr;
}

// ---------------- generic batched (complex) GEMM --------------------------
// MODE 0: C(cplx) = A(real, batched) * B(cplx, shared)
// MODE 1: C(cplx) = A(cplx, shared) * B(cplx, batched)
// MODE 2: C(real) = Re( A(cplx, batched) * B(cplx, shared) ), optional blend
template<int MODE, bool BLEND>
__global__ void __launch_bounds__(256) k_gemm(
    const float* __restrict__ Apr, const float* __restrict__ Api, long sA,
    const float* __restrict__ Bpr, const float* __restrict__ Bpi, long sB,
    float* Cpr, float* Cpi, long sC,
    int M, int Nn, int K, int lda, int ldb, int ldc,
    const float* __restrict__ v0, const float* __restrict__ v1)
{
    __shared__ float sAr[16][68];
    __shared__ float sAi[16][68];
    __shared__ float sBr[16][68];
    __shared__ float sBi[16][68];

    const int z = blockIdx.z;
    const float* Ar = Apr + (long)z * sA;
    const float* Ai = (MODE != 0) ? (Api + (long)z * sA) : nullptr;
    const float* Br = Bpr + (long)z * sB;
    const float* Bi = Bpi + (long)z * sB;
    float* Cr = Cpr + (long)z * sC;
    float* Ci = (MODE == 2) ? nullptr : (Cpi + (long)z * sC);

    const int row0 = blockIdx.y * 64;
    const int col0 = blockIdx.x * 64;
    const int tx = threadIdx.x, ty = threadIdx.y;
    const int tid = ty * 16 + tx;

    float accr[4][4] = {};
    float acci[4][4] = {};

    const int am = tid >> 2;         // 0..63 (A tile row)
    const int ak = (tid & 3) * 4;    // 0,4,8,12 (A tile k)
    const int bk = tid >> 4;         // 0..15 (B tile k)
    const int bn = (tid & 15) * 4;   // 0..60 (B tile col)

    for (int k0 = 0; k0 < K; k0 += 16) {
        // A tile -> transposed smem [k][m]
        {
            int row = row0 + am;
            bool rok = (row < M);
            #pragma unroll
            for (int s = 0; s < 2; s++) {
                int kkg = k0 + ak + 2 * s;
                float2 vr = make_float2(0.f, 0.f), vi = make_float2(0.f, 0.f);
                if (rok && kkg < K) {
                    vr = *(const float2*)(Ar + (long)row * lda + kkg);
                    if (MODE != 0) vi = *(const float2*)(Ai + (long)row * lda + kkg);
                }
                sAr[ak + 2 * s][am] = vr.x; sAr[ak + 2 * s + 1][am] = vr.y;
                if (MODE != 0) {
                    sAi[ak + 2 * s][am] = vi.x; sAi[ak + 2 * s + 1][am] = vi.y;
                }
            }
        }
        // B tile [k][n]
        {
            int krow = k0 + bk;
            bool kok = (krow < K);
            #pragma unroll
            for (int s = 0; s < 2; s++) {
                int col = col0 + bn + 2 * s;
                float2 vr = make_float2(0.f, 0.f), vi = make_float2(0.f, 0.f);
                if (kok && col < Nn) {
                    vr = *(const float2*)(Br + (long)krow * ldb + col);
                    vi = *(const float2*)(Bi + (long)krow * ldb + col);
                }
                sBr[bk][bn + 2 * s] = vr.x; sBr[bk][bn + 2 * s + 1] = vr.y;
                sBi[bk][bn + 2 * s] = vi.x; sBi[bk][bn + 2 * s + 1] = vi.y;
            }
        }
        __syncthreads();

        #pragma unroll
        for (int kk = 0; kk < 16; kk++) {
            float ar[4], aiv[4], br[4], biv[4];
            *(float4*)ar  = *(const float4*)&sAr[kk][ty * 4];
            if (MODE != 0) *(float4*)aiv = *(const float4*)&sAi[kk][ty * 4];
            *(float4*)br  = *(const float4*)&sBr[kk][tx * 4];
            *(float4*)biv = *(const float4*)&sBi[kk][tx * 4];
            #pragma unroll
            for (int i = 0; i < 4; i++)
                #pragma unroll
                for (int j = 0; j < 4; j++) {
                    if (MODE == 0) {
                        accr[i][j] += ar[i] * br[j];
                        acci[i][j] += ar[i] * biv[j];
                    } else if (MODE == 1) {
                        accr[i][j] += ar[i] * br[j] - aiv[i] * biv[j];
                        acci[i][j] += ar[i] * biv[j] + aiv[i] * br[j];
                    } else {
                        accr[i][j] += ar[i] * br[j] - aiv[i] * biv[j];
                    }
                }
        }
        __syncthreads();
    }

    const float* v0b = nullptr;
    const float* v1b = nullptr;
    if (BLEND) { v0b = v0 + (z / CH) * N2; v1b = v1 + (z / CH) * N2; }

    #pragma unroll
    for (int i = 0; i < 4; i++) {
        int row = row0 + ty * 4 + i;
        if (row >= M) continue;
        #pragma unroll
        for (int j = 0; j < 4; j++) {
            int col = col0 + tx * 4 + j;
            if (col >= Nn) continue;
            long off = (long)row * ldc + col;
            if (MODE == 2) {
                if (BLEND) {
                    float a = v0b[row] * v1b[col];
                    Cr[off] = a * Cr[off] + (1.f - a) * accr[i][j];
                } else {
                    Cr[off] = accr[i][j];
                }
            } else {
                Cr[off] = accr[i][j];
                Ci[off] = acci[i][j];
            }
        }
    }
}

// ---------------- host orchestration --------------------------------------
extern "C" void kernel_launch(void* const* d_in, const int* in_sizes, int n_in,
                              void* d_out, int out_size)
{
    const float *y = nullptr, *kk = nullptr, *lam = nullptr, *filt = nullptr;
    for (int i = 0; i < n_in; i++) {
        if      (in_sizes[i] == BATCH * CH * HIN * HIN) y    = (const float*)d_in[i];
        else if (in_sizes[i] == BATCH * KH * KH)        kk   = (const float*)d_in[i];
        else if (in_sizes[i] == 1)                      lam  = (const float*)d_in[i];
        else if (in_sizes[i] == NF * CH * FS * FS)      filt = (const float*)d_in[i];
    }
    float* out = (float*)d_out;

    float *Wfr, *Wfi, *Wir, *Wii, *W2r, *W2i, *x, *Gr, *Gi, *Fr, *Fi, *Zr, *Zi, *v0, *v1;
    cudaGetSymbolAddress((void**)&Wfr, g_Wfr);
    cudaGetSymbolAddress((void**)&Wfi, g_Wfi);
    cudaGetSymbolAddress((void**)&Wir, g_Wir);
    cudaGetSymbolAddress((void**)&Wii, g_Wii);
    cudaGetSymbolAddress((void**)&W2r, g_W2r);
    cudaGetSymbolAddress((void**)&W2i, g_W2i);
    cudaGetSymbolAddress((void**)&x,   g_x);
    cudaGetSymbolAddress((void**)&Gr,  g_Gr);
    cudaGetSymbolAddress((void**)&Gi,  g_Gi);
    cudaGetSymbolAddress((void**)&Fr,  g_Fr);
    cudaGetSymbolAddress((void**)&Fi,  g_Fi);
    cudaGetSymbolAddress((void**)&Zr,  g_Zr);
    cudaGetSymbolAddress((void**)&Zi,  g_Zi);
    cudaGetSymbolAddress((void**)&v0,  g_v0);
    cudaGetSymbolAddress((void**)&v1,  g_v1);

    const int tpb = 256;
    k_buildW <<<(NPIX + tpb - 1) / tpb, tpb>>>();
    k_buildW2<<<(NH * N2 + tpb - 1) / tpb, tpb>>>();
    k_buildE <<<(N2 * KH + tpb - 1) / tpb, tpb>>>();
    k_buildE3<<<(N2 * FS + tpb - 1) / tpb, tpb>>>();
    k_pad    <<<(NB * NPIX + tpb - 1) / tpb, tpb>>>(y);
    k_alpha  <<<2 * BATCH, 576>>>(kk);
    k_dk_a   <<<(BATCH * N2 * KH + tpb - 1) / tpb, tpb>>>(kk);
    k_dk_b   <<<(BATCH * HPIX + tpb - 1) / tpb, tpb>>>();
    k_dg     <<<(CH * HPIX + tpb - 1) / tpb, tpb>>>(filt);

    dim3 blk(16, 16);
    dim3 gFwd((NH + 63) / 64, (N2 + 63) / 64, NB);   // 5 x 9 x 24
    dim3 gInv2((N2 + 63) / 64, (N2 + 63) / 64, NB);  // 9 x 9 x 24
    int gpw = (NB * HPIX + tpb - 1) / tpb;

    for (int it = 0; it < 4; it++) {
        bool last = (it == 3);
        // forward stage 1: G[m,v] = sum_n x[m,n] * Wf[n,v]  (half columns)
        k_gemm<0, false><<<gFwd, blk>>>(x, nullptr, (long)NPIX,
                                        Wfr, Wfi, 0L,
                                        Gr, Gi, (long)HPIX,
                                        N2, NH, N2, N2, N2, NH, nullptr, nullptr);
        // forward stage 2: F[u,v] = sum_m Wf[u,m] * G[m,v]
        k_gemm<1, false><<<gFwd, blk>>>(Wfr, Wfi, 0L,
                                        Gr, Gi, (long)HPIX,
                                        Fr, Fi, (long)HPIX,
                                        N2, NH, N2, N2, NH, NH, nullptr, nullptr);
        if (!last) k_p1<<<gpw, tpb>>>();
        else       k_p3<<<gpw, tpb>>>(lam);
        // inverse stage 1: Z[m,v] = sum_u Wi[m,u] * F[u,v]
        k_gemm<1, false><<<gFwd, blk>>>(Wir, Wii, 0L,
                                        Fr, Fi, (long)HPIX,
                                        Zr, Zi, (long)HPIX,
                                        N2, NH, N2, N2, NH, NH, nullptr, nullptr);
        // inverse stage 2 (real): x/out[m,n] = Re( sum_v Z[m,v] * W2[v,n] )
        if (!last)
            k_gemm<2, true><<<gInv2, blk>>>(Zr, Zi, (long)HPIX,
                                            W2r, W2i, 0L,
                                            x, nullptr, (long)NPIX,
                                            N2, N2, NH, NH, N2, N2, v0, v1);
        else
            k_gemm<2, false><<<gInv2, blk>>>(Zr, Zi, (long)HPIX,
                                             W2r, W2i, 0L,
                                             out, nullptr, (long)NPIX,
                                             N2, N2, NH, NH, N2, N2, nullptr, nullptr);
    }
    (void)out_size;
}

// round 5
// speedup vs baseline: 1.2237x; 1.2234x over previous
#include <cuda_runtime.h>
#include <cuda_bf16.h>
#include <mma.h>
#include <math.h>

using namespace nvcuda;

#define N2   542
#define NH   272
#define NPIX (N2*N2)
#define HPIX (N2*NH)
#define NB   24
#define BATCH 8
#define CH   3
#define HIN  512
#define KH   31
#define PH   15
#define FS   3
#define NF   8
#define L1   541

#define LDN  544             // packed B width (Re 0..271 | Im 272..543)
#define LDW  640             // padded C width
#define MPAD 640             // padded C rows
#define SIMG (MPAD*LDW)      // per-image padded C stride
#define KP1  1632
#define KP2  3264

// ---------------- device global scratch -----------------------------------
__device__ float g_Wfr[NPIX], g_Wfi[NPIX];
__device__ float g_Wir[NPIX], g_Wii[NPIX];
__device__ float g_W2r[NH*N2], g_W2i[NH*N2];
__device__ float g_x  [NB*SIMG];
__device__ float g_G  [NB*SIMG];
__device__ float g_F  [NB*SIMG];
__device__ float g_Z  [NB*SIMG];
__device__ float g_Dkr[BATCH*HPIX], g_Dki[BATCH*HPIX];
__device__ float g_Dg [CH*HPIX];
__device__ float g_v0 [BATCH*N2], g_v1 [BATCH*N2];
__device__ float g_Er [N2*KH], g_Ei [N2*KH];
__device__ float g_E3r[N2*FS], g_E3i[N2*FS];
__device__ float g_Tr [BATCH*N2*KH], g_Ti[BATCH*N2*KH];

__device__ __nv_bfloat16 g_pF1A[(size_t)NB*N2*KP1];
__device__ __nv_bfloat16 g_pF1B[(size_t)KP1*LDN];
__device__ __nv_bfloat16 g_pWfA[(size_t)N2*KP2];
__device__ __nv_bfloat16 g_pWiA[(size_t)N2*KP2];
__device__ __nv_bfloat16 g_pCB [(size_t)NB*KP2*LDN];
__device__ __nv_bfloat16 g_pI2A[(size_t)NB*N2*KP1];
__device__ __nv_bfloat16 g_pI2B[(size_t)KP1*LDN];

// ---------------- setup kernels -------------------------------------------
__global__ void k_buildW() {
    int idx = blockIdx.x * blockDim.x + threadIdx.x;
    if (idx >= NPIX) return;
    int kc = idx % N2, j = idx / N2;
    long t = ((long)j * kc) % N2;
    double sn, cs;
    sincospi(2.0 * (double)t / (double)N2, &sn, &cs);
    g_Wfr[idx] = (float)cs;            g_Wfi[idx] = (float)(-sn);
    g_Wir[idx] = (float)(cs / N2);     g_Wii[idx] = (float)(sn / N2);
}

__global__ void k_buildW2() {
    int idx = blockIdx.x * blockDim.x + threadIdx.x;
    if (idx >= NH * N2) return;
    int n = idx % N2, v = idx / N2;
    long t = ((long)v * n) % N2;
    double sn, cs;
    sincospi(2.0 * (double)t / (double)N2, &sn, &cs);
    double w = ((v == 0) || (v == NH - 1)) ? (1.0 / N2) : (2.0 / N2);
    g_W2r[idx] = (float)(cs * w);
    g_W2i[idx] = (float)(sn * w);
}

__global__ void k_buildE() {
    int idx = blockIdx.x * blockDim.x + threadIdx.x;
    if (idx >= N2 * KH) return;
    int t = idx % KH, u = idx / KH;
    long m = ((long)u * (t - PH)) % N2; if (m < 0) m += N2;
    double sn, cs;
    sincospi(2.0 * (double)m / (double)N2, &sn, &cs);
    g_Er[idx] = (float)cs; g_Ei[idx] = (float)(-sn);
}

__global__ void k_buildE3() {
    int idx = blockIdx.x * blockDim.x + threadIdx.x;
    if (idx >= N2 * FS) return;
    int t = idx % FS, u = idx / FS;
    long m = ((long)u * (t - 1)) % N2; if (m < 0) m += N2;
    double sn, cs;
    sincospi(2.0 * (double)m / (double)N2, &sn, &cs);
    g_E3r[idx] = (float)cs; g_E3i[idx] = (float)(-sn);
}

__global__ void k_pad(const float* __restrict__ y) {
    int idx = blockIdx.x * blockDim.x + threadIdx.x;
    if (idx >= NB * NPIX) return;
    int jj = idx % N2, ii = (idx / N2) % N2, img = idx / NPIX;
    int si = min(max(ii - PH, 0), HIN - 1);
    int sj = min(max(jj - PH, 0), HIN - 1);
    g_x[(size_t)img * SIMG + (size_t)ii * LDW + jj] =
        y[(long)img * HIN * HIN + si * HIN + sj];
}

__global__ void k_alpha(const float* __restrict__ kk) {
    int b = blockIdx.x >> 1;
    int axis = blockIdx.x & 1;
    __shared__ float proj[KH];
    __shared__ float p[L1];
    __shared__ float cb[L1];
    __shared__ float red[576];
    int tid = threadIdx.x;

    if (tid < KH) {
        float s = 0.f;
        const float* kb = kk + b * KH * KH;
        for (int t = 0; t < KH; t++)
            s += (axis == 0) ? kb[tid * KH + t] : kb[t * KH + tid];
        proj[tid] = s;
    }
    __syncthreads();

    if (tid < L1) {
        double zr = 0.0, zi = 0.0;
        for (int t = 0; t < KH; t++) {
            int m = (tid * t) % L1;
            double sn, cs;
            sincospi(2.0 * (double)m / (double)L1, &sn, &cs);
            zr += proj[t] * cs;
            zi -= proj[t] * sn;
        }
        p[tid] = (float)(zr * zr + zi * zi);
    }
    __syncthreads();

    if (tid < L1) {
        double acc = 0.0;
        for (int m = 0; m < L1; m++) {
            int mm = (m * tid) % L1;
            double sn, cs;
            sincospi(2.0 * (double)mm / (double)L1, &sn, &cs);
            acc += (double)p[m] * cs;
        }
        cb[tid] = (float)(acc / (double)L1);
    }
    red[tid] = (tid < L1) ? cb[tid] : -1e30f;
    __syncthreads();
    for (int s = 512; s > 0; s >>= 1) {
        if (tid < s && tid + s < 576) red[tid] = fmaxf(red[tid], red[tid + s]);
        __syncthreads();
    }
    float mx = red[0];
    float* v = (axis == 0) ? (g_v0 + b * N2) : (g_v1 + b * N2);
    if (tid < L1) v[tid] = 1.f - cb[tid] / mx;
    if (tid == 0) v[L1] = 1.f - cb[0] / mx;
}

__global__ void k_dk_a(const float* __restrict__ kk) {
    int idx = blockIdx.x * blockDim.x + threadIdx.x;
    if (idx >= BATCH * N2 * KH) return;
    int j = idx % KH;
    int u = (idx / KH) % N2;
    int b = idx / (KH * N2);
    float tr = 0.f, ti = 0.f;
    for (int i = 0; i < KH; i++) {
        float w = kk[b * KH * KH + i * KH + j];
        tr += w * g_Er[u * KH + i];
        ti += w * g_Ei[u * KH + i];
    }
    g_Tr[idx] = tr; g_Ti[idx] = ti;
}

__global__ void k_dk_b() {
    int idx = blockIdx.x * blockDim.x + threadIdx.x;
    if (idx >= BATCH * HPIX) return;
    int v = idx % NH;
    int u = (idx / NH) % N2;
    int b = idx / HPIX;
    float dr = 0.f, di = 0.f;
    const float* tr = g_Tr + (b * N2 + u) * KH;
    const float* ti = g_Ti + (b * N2 + u) * KH;
    for (int j = 0; j < KH; j++) {
        float er = g_Er[v * KH + j], ei = g_Ei[v * KH + j];
        dr += tr[j] * er - ti[j] * ei;
        di += tr[j] * ei + ti[j] * er;
    }
    g_Dkr[idx] = dr; g_Dki[idx] = di;
}

__global__ void k_dg(const float* __restrict__ filt) {
    int idx = blockIdx.x * blockDim.x + threadIdx.x;
    if (idx >= CH * HPIX) return;
    int v = idx % NH;
    int u = (idx / NH) % N2;
    int c = idx / HPIX;
    float eur[FS], eui[FS], evr[FS], evi[FS];
    for (int t = 0; t < FS; t++) {
        eur[t] = g_E3r[u * FS + t]; eui[t] = g_E3i[u * FS + t];
        evr[t] = g_E3r[v * FS + t]; evi[t] = g_E3i[v * FS + t];
    }
    float acc = 0.f;
    for (int f = 0; f < NF; f++) {
        float cr = 0.f, ci = 0.f;
        for (int i = 0; i < FS; i++)
            for (int j = 0; j < FS; j++) {
                float w = filt[((f * CH + c) * FS + i) * FS + j];
                float er = eur[i] * evr[j] - eui[i] * evi[j];
                float ei = eur[i] * evi[j] + eui[i] * evr[j];
                cr += w * er; ci += w * ei;
            }
        acc += cr * cr + ci * ci;
    }
    g_Dg[idx] = acc;
}

// pointwise spectrum ops on g_F layout [img][u][v | 272+v], row stride LDW
__global__ void k_p1() {
    int idx = blockIdx.x * blockDim.x + threadIdx.x;
    if (idx >= NB * N2 * NH) return;
    int v = idx % NH;
    int u = (idx / NH) % N2;
    int img = idx / (NH * N2);
    int b = img / CH;
    float dr = g_Dkr[b * HPIX + u * NH + v], di = g_Dki[b * HPIX + u * NH + v];
    float* Fp = g_F + (size_t)img * SIMG + (size_t)u * LDW + v;
    float fr = Fp[0], fi = Fp[NH];
    Fp[0]  = fr * dr - fi * di;
    Fp[NH] = fr * di + fi * dr;
}

__global__ void k_p3(const float* __restrict__ lam) {
    int idx = blockIdx.x * blockDim.x + threadIdx.x;
    if (idx >= NB * N2 * NH) return;
    float el = expf(lam[0]);
    int v = idx % NH;
    int u = (idx / NH) % N2;
    int img = idx / (NH * N2);
    int b = img / CH, c = img % CH;
    float dr = g_Dkr[b * HPIX + u * NH + v], di = g_Dki[b * HPIX + u * NH + v];
    float om = 1.f / (dr * dr + di * di + el * g_Dg[c * HPIX + u * NH + v]);
    float mr = dr * om, mi = -di * om;
    float* Fp = g_F + (size_t)img * SIMG + (size_t)u * LDW + v;
    float fr = Fp[0], fi = Fp[NH];
    Fp[0]  = fr * mr - fi * mi;
    Fp[NH] = fr * mi + fi * mr;
}

// ---------------- split-bf16 pack kernels ----------------------------------
__device__ __forceinline__ __nv_bfloat16 splitpick(float v, bool lo) {
    __nv_bfloat16 h = __float2bfloat16(v);
    if (!lo) return h;
    return __float2bfloat16(v - __bfloat162float(h));
}

__global__ void k_packF1B() {
    int idx = blockIdx.x * blockDim.x + threadIdx.x;
    if (idx >= KP1 * LDN) return;
    int c = idx % LDN, r = idx / LDN;
    __nv_bfloat16 o = __float2bfloat16(0.f);
    if (r < 3 * N2) {
        int b = r / N2, k = r % N2;
        float val = (c < NH) ? g_Wfr[k * N2 + c] : g_Wfi[k * N2 + (c - NH)];
        o = splitpick(val, b == 1);
    }
    g_pF1B[idx] = o;
}

__global__ void k_packWA(__nv_bfloat16* dst, const float* __restrict__ srcR,
                         const float* __restrict__ srcI) {
    int idx = blockIdx.x * blockDim.x + threadIdx.x;
    if (idx >= N2 * KP2) return;
    int q = idx % KP2, m = idx / KP2;
    __nv_bfloat16 o = __float2bfloat16(0.f);
    if (q < 6 * N2) {
        int b = q / N2, j = q % N2;
        float val = (b < 3) ? srcR[m * N2 + j] : srcI[m * N2 + j];
        o = splitpick(val, (b == 2) || (b == 5));
    }
    dst[idx] = o;
}

__global__ void k_packCB(const float* __restrict__ S) {
    size_t idx = (size_t)blockIdx.x * blockDim.x + threadIdx.x;
    if (idx >= (size_t)NB * KP2 * LDN) return;
    int c = (int)(idx % LDN);
    int r = (int)((idx / LDN) % KP2);
    int img = (int)(idx / ((size_t)KP2 * LDN));
    __nv_bfloat16 o = __float2bfloat16(0.f);
    if (r < 6 * N2) {
        int b = r / N2, k = r % N2;
        int v = (c < NH) ? c : (c - NH);
        const float* row = S + (size_t)img * SIMG + (size_t)k * LDW;
        float sr = row[v], si = row[NH + v];
        float val;
        if (c < NH) { val = (b < 3) ? sr : -si; }
        else        { val = (b < 3) ? si :  sr; }
        o = splitpick(val, (b == 1) || (b == 4));
    }
    g_pCB[idx] = o;
}

__global__ void k_packF1A() {
    size_t idx = (size_t)blockIdx.x * blockDim.x + threadIdx.x;
    if (idx >= (size_t)NB * N2 * KP1) return;
    int q = (int)(idx % KP1);
    int m = (int)((idx / KP1) % N2);
    int img = (int)(idx / ((size_t)N2 * KP1));
    __nv_bfloat16 o = __float2bfloat16(0.f);
    if (q < 3 * N2) {
        int b = q / N2, n = q % N2;
        float val = g_x[(size_t)img * SIMG + (size_t)m * LDW + n];
        o = splitpick(val, b == 2);
    }
    g_pF1A[idx] = o;
}

__global__ void k_packI2A() {
    size_t idx = (size_t)blockIdx.x * blockDim.x + threadIdx.x;
    if (idx >= (size_t)NB * N2 * KP1) return;
    int q = (int)(idx % KP1);
    int m = (int)((idx / KP1) % N2);
    int img = (int)(idx / ((size_t)N2 * KP1));
    int b = q / NH, k = q % NH;
    const float* row = g_Z + (size_t)img * SIMG + (size_t)m * LDW;
    float val = (b < 3) ? row[k] : row[NH + k];
    g_pI2A[idx] = splitpick(val, (b == 2) || (b == 5));
}

__global__ void k_packI2B() {
    int idx = blockIdx.x * blockDim.x + threadIdx.x;
    if (idx >= KP1 * LDN) return;
    int c = idx % LDN, r = idx / LDN;
    __nv_bfloat16 o = __float2bfloat16(0.f);
    if (c < N2) {
        int b = r / NH, v = r % NH;
        float val = (b < 3) ? g_W2r[v * N2 + c] : -g_W2i[v * N2 + c];
        o = splitpick(val, (b == 1) || (b == 4));
    }
    g_pI2B[idx] = o;
}

__global__ void k_copyout(float* __restrict__ out) {
    int idx = blockIdx.x * blockDim.x + threadIdx.x;
    if (idx >= NB * NPIX) return;
    int j = idx % N2, i = (idx / N2) % N2, img = idx / NPIX;
    out[idx] = g_G[(size_t)img * SIMG + (size_t)i * LDW + j];
}

// ---------------- WMMA bf16 GEMM -------------------------------------------
// C[M x N(pad)] fp32 = A[M x Kp] bf16 * B[Kp x Npad] bf16, all row-major.
// C buffers are padded (rows MPAD, width ldc) so full 16x16 tiles store safely.
// blend=1: C = a*C + (1-a)*acc with a = v0[row]*v1[col], bounds-checked.
__global__ void __launch_bounds__(256) k_wmma(
    const __nv_bfloat16* __restrict__ Ag, long strideA, int lda,
    const __nv_bfloat16* __restrict__ Bg, long strideB, int ldb,
    float* Cg, long strideC, int ldc,
    int M, int Kp, int blend,
    const float* __restrict__ v0, const float* __restrict__ v1)
{
    __shared__ __align__(16) __nv_bfloat16 shA[128 * 40];
    __shared__ __align__(16) __nv_bfloat16 shB[32 * 136];
    __shared__ __align__(16) float shP[8 * 16 * 20];

    const int tid  = threadIdx.x;
    const int lane = tid & 31;
    const int wid  = tid >> 5;
    const int wm   = wid >> 2;       // 0..1
    const int wn   = wid & 3;        // 0..3
    const int z    = blockIdx.z;
    const int row0 = blockIdx.y * 128;
    const int col0 = blockIdx.x * 128;

    const __nv_bfloat16* A = Ag + (size_t)z * strideA;
    const __nv_bfloat16* B = Bg + (size_t)z * strideB;
    float* C = Cg + (size_t)z * strideC;

    wmma::fragment<wmma::accumulator, 16, 16, 16, float> cf[4][2];
    for (int mt = 0; mt < 4; mt++)
        for (int nt = 0; nt < 2; nt++)
            wmma::fill_fragment(cf[mt][nt], 0.f);

    for (int k0 = 0; k0 < Kp; k0 += 32) {
        // stage A tile 128x32
        for (int i = 0; i < 2; i++) {
            int idx = tid + i * 256;
            int r = idx >> 2, c = (idx & 3) * 8;
            int gr = row0 + r; if (gr > M - 1) gr = M - 1;
            const float4* src = (const float4*)(A + (size_t)gr * lda + k0 + c);
            *(float4*)(shA + r * 40 + c) = *src;
        }
        // stage B tile 32x128
        for (int i = 0; i < 2; i++) {
            int idx = tid + i * 256;
            int r = idx >> 4, c = (idx & 15) * 8;
            int gc = col0 + c; if (gc > ldb - 8) gc = ldb - 8;
            const float4* src = (const float4*)(B + (size_t)(k0 + r) * ldb + gc);
            *(float4*)(shB + r * 136 + c) = *src;
        }
        __syncthreads();

        for (int kk = 0; kk < 32; kk += 16) {
            wmma::fragment<wmma::matrix_b, 16, 16, 16, __nv_bfloat16, wmma::row_major> bf0;
            wmma::fragment<wmma::matrix_b, 16, 16, 16, __nv_bfloat16, wmma::row_major> bf1;
            wmma::load_matrix_sync(bf0, shB + kk * 136 + wn * 32, 136);
            wmma::load_matrix_sync(bf1, shB + kk * 136 + wn * 32 + 16, 136);
            for (int mt = 0; mt < 4; mt++) {
                wmma::fragment<wmma::matrix_a, 16, 16, 16, __nv_bfloat16, wmma::row_major> af;
                wmma::load_matrix_sync(af, shA + (wm * 64 + mt * 16) * 40 + kk, 40);
                wmma::mma_sync(cf[mt][0], af, bf0, cf[mt][0]);
                wmma::mma_sync(cf[mt][1], af, bf1, cf[mt][1]);
            }
        }
        __syncthreads();
    }

    if (blend == 0) {
        for (int mt = 0; mt < 4; mt++) {
            for (int nt = 0; nt < 2; nt++) {
                int gr = row0 + wm * 64 + mt * 16;
                int gc = col0 + wn * 32 + nt * 16;
                wmma::store_matrix_sync(C + (size_t)gr * ldc + gc, cf[mt][nt],
                                        ldc, wmma::mem_row_major);
            }
        }
    } else {
        const float* v0b = v0 + (z / CH) * N2;
        const float* v1b = v1 + (z / CH) * N2;
        float* patch = shP + wid * 16 * 20;
        for (int mt = 0; mt < 4; mt++) {
            for (int nt = 0; nt < 2; nt++) {
                wmma::store_matrix_sync(patch, cf[mt][nt], 20, wmma::mem_row_major);
                __syncwarp();
                int gr0 = row0 + wm * 64 + mt * 16;
                int gc0 = col0 + wn * 32 + nt * 16;
                for (int e = lane; e < 256; e += 32) {
                    int r = e >> 4, c = e & 15;
                    int row = gr0 + r, col = gc0 + c;
                    if (row < N2 && col < N2) {
                        float a = v0b[row] * v1b[col];
                        size_t off = (size_t)row * ldc + col;
                        C[off] = a * C[off] + (1.f - a) * patch[r * 20 + c];
                    }
                }
                __syncwarp();
            }
        }
    }
}

// ---------------- host orchestration --------------------------------------
extern "C" void kernel_launch(void* const* d_in, const int* in_sizes, int n_in,
                              void* d_out, int out_size)
{
    const float *y = 0, *kk = 0, *lam = 0, *filt = 0;
    for (int i = 0; i < n_in; i++) {
        if      (in_sizes[i] == BATCH * CH * HIN * HIN) y    = (const float*)d_in[i];
        else if (in_sizes[i] == BATCH * KH * KH)        kk   = (const float*)d_in[i];
        else if (in_sizes[i] == 1)                      lam  = (const float*)d_in[i];
        else if (in_sizes[i] == NF * CH * FS * FS)      filt = (const float*)d_in[i];
    }
    float* out = (float*)d_out;

    float *Wfr, *Wfi, *Wir, *Wii, *x, *G, *F, *Z, *v0, *v1;
    __nv_bfloat16 *pF1A, *pF1B, *pWfA, *pWiA, *pCB, *pI2A, *pI2B;
    cudaGetSymbolAddress((void**)&Wfr, g_Wfr);
    cudaGetSymbolAddress((void**)&Wfi, g_Wfi);
    cudaGetSymbolAddress((void**)&Wir, g_Wir);
    cudaGetSymbolAddress((void**)&Wii, g_Wii);
    cudaGetSymbolAddress((void**)&x,   g_x);
    cudaGetSymbolAddress((void**)&G,   g_G);
    cudaGetSymbolAddress((void**)&F,   g_F);
    cudaGetSymbolAddress((void**)&Z,   g_Z);
    cudaGetSymbolAddress((void**)&v0,  g_v0);
    cudaGetSymbolAddress((void**)&v1,  g_v1);
    cudaGetSymbolAddress((void**)&pF1A, g_pF1A);
    cudaGetSymbolAddress((void**)&pF1B, g_pF1B);
    cudaGetSymbolAddress((void**)&pWfA, g_pWfA);
    cudaGetSymbolAddress((void**)&pWiA, g_pWiA);
    cudaGetSymbolAddress((void**)&pCB,  g_pCB);
    cudaGetSymbolAddress((void**)&pI2A, g_pI2A);
    cudaGetSymbolAddress((void**)&pI2B, g_pI2B);

    const int tpb = 256;
    k_buildW <<<(NPIX + tpb - 1) / tpb, tpb>>>();
    k_buildW2<<<(NH * N2 + tpb - 1) / tpb, tpb>>>();
    k_buildE <<<(N2 * KH + tpb - 1) / tpb, tpb>>>();
    k_buildE3<<<(N2 * FS + tpb - 1) / tpb, tpb>>>();
    k_pad    <<<(NB * NPIX + tpb - 1) / tpb, tpb>>>(y);
    k_alpha  <<<2 * BATCH, 576>>>(kk);
    k_dk_a   <<<(BATCH * N2 * KH + tpb - 1) / tpb, tpb>>>(kk);
    k_dk_b   <<<(BATCH * HPIX + tpb - 1) / tpb, tpb>>>();
    k_dg     <<<(CH * HPIX + tpb - 1) / tpb, tpb>>>(filt);

    k_packF1B<<<(KP1 * LDN + tpb - 1) / tpb, tpb>>>();
    k_packWA <<<(N2 * KP2 + tpb - 1) / tpb, tpb>>>(pWfA, Wfr, Wfi);
    k_packWA <<<(N2 * KP2 + tpb - 1) / tpb, tpb>>>(pWiA, Wir, Wii);
    k_packI2B<<<(KP1 * LDN + tpb - 1) / tpb, tpb>>>();

    const long nF1A = (long)NB * N2 * KP1;
    const long nCB  = (long)NB * KP2 * LDN;
    const int gpw = (NB * N2 * NH + tpb - 1) / tpb;

    dim3 gemmGrid(5, 5, NB);

    for (int it = 0; it < 4; it++) {
        int last = (it == 3);

        // F1: G = x * Wf   (M=542, N=544, K=1632)
        k_packF1A<<<(int)((nF1A + tpb - 1) / tpb), tpb>>>();
        k_wmma<<<gemmGrid, tpb>>>(pF1A, (long)N2 * KP1, KP1,
                                  pF1B, 0L, LDN,
                                  G, (long)SIMG, LDW,
                                  N2, KP1, 0, v0, v1);

        // F2: F = Wf * G   (K=3264)
        k_packCB<<<(int)((nCB + tpb - 1) / tpb), tpb>>>(G);
        k_wmma<<<gemmGrid, tpb>>>(pWfA, 0L, KP2,
                                  pCB, (long)KP2 * LDN, LDN,
                                  F, (long)SIMG, LDW,
                                  N2, KP2, 0, v0, v1);

        if (!last) k_p1<<<gpw, tpb>>>();
        else       k_p3<<<gpw, tpb>>>(lam);

        // I1: Z = Wi * F
        k_packCB<<<(int)((nCB + tpb - 1) / tpb), tpb>>>(F);
        k_wmma<<<gemmGrid, tpb>>>(pWiA, 0L, KP2,
                                  pCB, (long)KP2 * LDN, LDN,
                                  Z, (long)SIMG, LDW,
                                  N2, KP2, 0, v0, v1);

        // I2: x = blend(Re(Z * W2))  /  final: G = Re(Z * W2) then copy out
        k_packI2A<<<(int)((nF1A + tpb - 1) / tpb), tpb>>>();
        if (!last)
            k_wmma<<<gemmGrid, tpb>>>(pI2A, (long)N2 * KP1, KP1,
                                      pI2B, 0L, LDN,
                                      x, (long)SIMG, LDW,
                                      N2, KP1, 1, v0, v1);
        else {
            k_wmma<<<gemmGrid, tpb>>>(pI2A, (long)N2 * KP1, KP1,
                                      pI2B, 0L, LDN,
                                      G, (long)SIMG, LDW,
                                      N2, KP1, 0, v0, v1);
            k_copyout<<<(NB * NPIX + tpb - 1) / tpb, tpb>>>(out);
        }
    }
    (void)out_size;
}